// round 10
// baseline (speedup 1.0000x reference)
#include <cuda_runtime.h>
#include <cstdint>
#include <cstddef>

#define BATCH   8
#define NPTS    8192
#define CDIM    6
#define NG      512
#define GS      32
#define NSLAB   256
#define FULLMASK 0xffffffffu
#define PINF    __int_as_float(0x7f800000)

// output layout: neighborhood, center, idx (flattened tuple order, all f32)
#define NB_SZ  (BATCH * NG * GS * CDIM)   // 786432
#define C_OFF  (NB_SZ)
#define C_SZ   (BATCH * NG * 3)           // 12288
#define I_OFF  (C_OFF + C_SZ)             // 798720
#define I_SZ   (BATCH * NG * GS)          // 131072

// scratch (no allocations allowed -> __device__ globals)
__device__ float4 g_pts[BATCH * NPTS];    // original order: (x, y, z, |p|^2)
__device__ float4 g_spts[BATCH * NPTS];   // x-sorted order
__device__ int    g_sidx[BATCH * NPTS];   // sorted pos -> original index
__device__ float2 g_slab[BATCH * NSLAB];  // per-32-point slab (xmin, xmax)
__device__ float4 g_center[BATCH * NG];   // (cx, cy, cz, |c|^2)
__device__ int    g_prog[BATCH];          // highest published center index
__device__ int    g_sort_done[BATCH];

// ---------------------------------------------------------------------------
// packed f32x2 helpers (FFMA2; per-component RN rounding identical to scalar)
// ---------------------------------------------------------------------------
__device__ __forceinline__ unsigned long long pk2(float lo, float hi) {
    unsigned long long r;
    asm("mov.b64 %0, {%1, %2};" : "=l"(r)
        : "r"(__float_as_uint(lo)), "r"(__float_as_uint(hi)));
    return r;
}
__device__ __forceinline__ void upk2(unsigned long long v, float& lo, float& hi) {
    unsigned a, b;
    asm("mov.b64 {%0, %1}, %2;" : "=r"(a), "=r"(b) : "l"(v));
    lo = __uint_as_float(a); hi = __uint_as_float(b);
}
__device__ __forceinline__ unsigned long long add2(unsigned long long a, unsigned long long b) {
    unsigned long long r;
    asm("add.rn.f32x2 %0, %1, %2;" : "=l"(r) : "l"(a), "l"(b));
    return r;
}
__device__ __forceinline__ unsigned long long mul2(unsigned long long a, unsigned long long b) {
    unsigned long long r;
    asm("mul.rn.f32x2 %0, %1, %2;" : "=l"(r) : "l"(a), "l"(b));
    return r;
}
__device__ __forceinline__ unsigned long long fma2(unsigned long long a, unsigned long long b,
                                                   unsigned long long c) {
    unsigned long long r;
    asm("fma.rn.f32x2 %0, %1, %2, %3;" : "=l"(r) : "l"(a), "l"(b), "l"(c));
    return r;
}

__device__ __forceinline__ float sumsq3(float x, float y, float z) {
    float t = __fmul_rn(x, x);
    t = __fmaf_rn(y, y, t);
    t = __fmaf_rn(z, z, t);
    return t;
}

#define FT 512
// dynamic smem: sx, sy, sz (sorted), s_oidx, s_inv, partials
#define FPS_SMEM ((size_t)(5 * NPTS) * sizeof(float) + 256)

// static shared (per-CTA; roles use disjoint subsets)
__shared__ float  s_red[64];
__shared__ int    s_hist[NSLAB];
__shared__ float  s_mm[2];
__shared__ float2 k_slab[NSLAB];
__shared__ float  k_bufD[16][64];
__shared__ int    k_bufI[16][64];
__shared__ float  k_mD[8][32];
__shared__ int    k_mI[8][32];

// ---------------------------------------------------------------------------
// FPS role: load+transform, in-CTA x counting sort (publishes g_spts/g_sidx/
// g_slab + sort_done), then slab-pruned FPS. 16 warps x 4 slabs x 128 points.
// Slab skip iff 0.98*lb_x^2 > slabMax  => skipped dists provably unchanged =>
// selection bit-exact vs the proven full-update version. Update chain for
// touched slabs is byte-identical packed f32x2. Tie-break on ORIGINAL index.
// ---------------------------------------------------------------------------
__device__ void fps_role(const float* __restrict__ xyz, float* __restrict__ out,
                         int out_size, int b, char* dsm) {
    const int tid = threadIdx.x;
    const int lane = tid & 31, w = tid >> 5;
    float* sx = (float*)dsm;
    float* sy = sx + NPTS;
    float* sz = sy + NPTS;
    int* s_oidx = (int*)(sz + NPTS);      // sorted pos -> orig idx
    int* s_inv  = s_oidx + NPTS;          // orig idx -> sorted pos
    unsigned* sv    = (unsigned*)(s_inv + NPTS);   // [2][16] partial values
    unsigned* sidxp = sv + 32;                     // [2][16] partial indices

    // ---- load + transform + publish g_pts ----
    const float* base = xyz + (size_t)b * NPTS * CDIM;
    float xv[16], yv[16], zv[16];
    float lmin = PINF, lmax = -PINF;
#pragma unroll
    for (int j = 0; j < 16; j++) {
        int i = j * FT + tid;
        float x = base[i * CDIM + 0];
        float y = base[i * CDIM + 1];
        float z = base[i * CDIM + 2];
        xv[j] = x; yv[j] = y; zv[j] = z;
        g_pts[b * NPTS + i] = make_float4(x, y, z, sumsq3(x, y, z));
        lmin = fminf(lmin, x); lmax = fmaxf(lmax, x);
    }
#pragma unroll
    for (int off = 16; off > 0; off >>= 1) {
        lmin = fminf(lmin, __shfl_down_sync(FULLMASK, lmin, off));
        lmax = fmaxf(lmax, __shfl_down_sync(FULLMASK, lmax, off));
    }
    if (lane == 0) { s_red[w] = lmin; s_red[32 + w] = lmax; }
    if (tid < NSLAB) s_hist[tid] = 0;
    __syncthreads();
    if (tid < 32) {
        float a = (tid < 16) ? s_red[tid] : PINF;
        float c = (tid < 16) ? s_red[32 + tid] : -PINF;
#pragma unroll
        for (int off = 16; off > 0; off >>= 1) {
            a = fminf(a, __shfl_down_sync(FULLMASK, a, off));
            c = fmaxf(c, __shfl_down_sync(FULLMASK, c, off));
        }
        if (tid == 0) { s_mm[0] = a; s_mm[1] = c; }
    }
    __syncthreads();
    const float xmin0 = s_mm[0];
    const float scale = 255.0f / fmaxf(s_mm[1] - xmin0, 1e-20f);
    int bins[16];
#pragma unroll
    for (int j = 0; j < 16; j++) {
        int bn = (int)((xv[j] - xmin0) * scale);
        bins[j] = bn < 0 ? 0 : (bn > 255 ? 255 : bn);
        atomicAdd(&s_hist[bins[j]], 1);
    }
    __syncthreads();
    if (tid < 32) {                       // exclusive prefix over 256 bins
        int v[8], s = 0;
#pragma unroll
        for (int r = 0; r < 8; r++) { v[r] = s_hist[tid * 8 + r]; s += v[r]; }
        int inc = s;
#pragma unroll
        for (int off = 1; off < 32; off <<= 1) {
            int n = __shfl_up_sync(FULLMASK, inc, off);
            if (tid >= off) inc += n;
        }
        int run = inc - s;
#pragma unroll
        for (int r = 0; r < 8; r++) { int t = v[r]; s_hist[tid * 8 + r] = run; run += t; }
    }
    __syncthreads();
#pragma unroll
    for (int j = 0; j < 16; j++) {
        int i = j * FT + tid;
        int pos = atomicAdd(&s_hist[bins[j]], 1);
        sx[pos] = xv[j]; sy[pos] = yv[j]; sz[pos] = zv[j];
        s_oidx[pos] = i; s_inv[i] = pos;
        g_spts[b * NPTS + pos] = make_float4(xv[j], yv[j], zv[j], sumsq3(xv[j], yv[j], zv[j]));
        g_sidx[b * NPTS + pos] = i;
    }
    __syncthreads();
    if (tid < NSLAB) {                    // 32-pt slab bounds (kNN + fps derive)
        float mn = PINF, mx = -PINF;
#pragma unroll 8
        for (int r = 0; r < 32; r++) {
            float x = sx[tid * 32 + r];
            mn = fminf(mn, x); mx = fmaxf(mx, x);
        }
        float2 mm = make_float2(mn, mx);
        k_slab[tid] = mm;
        g_slab[b * NSLAB + tid] = mm;
    }
    __threadfence();
    __syncthreads();
    if (tid == 0) atomicExch(&g_sort_done[b], 1);

    // ---- slab register init: warp w owns fps-slabs 4w..4w+3 (128 pts each) ----
    unsigned long long P[4][6];           // per slab: xA,yA,zA (r0,r1), xB,yB,zB (r2,r3)
    float D[16];                          // dist, slab s point r -> D[4s+r]
    unsigned SMb[4];                      // slabMax bits (warp-uniform)
    float SXm[4], SXM[4];                 // fps-slab x bounds
#pragma unroll
    for (int s = 0; s < 4; s++) {
        const int fs = w * 4 + s;
        const int p0 = fs * 128 + lane;
        float x0 = sx[p0], x1 = sx[p0 + 32], x2 = sx[p0 + 64], x3 = sx[p0 + 96];
        float y0 = sy[p0], y1 = sy[p0 + 32], y2 = sy[p0 + 64], y3 = sy[p0 + 96];
        float z0 = sz[p0], z1 = sz[p0 + 32], z2 = sz[p0 + 64], z3 = sz[p0 + 96];
        P[s][0] = pk2(x0, x1); P[s][1] = pk2(y0, y1); P[s][2] = pk2(z0, z1);
        P[s][3] = pk2(x2, x3); P[s][4] = pk2(y2, y3); P[s][5] = pk2(z2, z3);
        D[4 * s + 0] = PINF; D[4 * s + 1] = PINF; D[4 * s + 2] = PINF; D[4 * s + 3] = PINF;
        SMb[s] = 0x7f800000u;             // +inf
        float mn = PINF, mx = -PINF;
#pragma unroll
        for (int r = 0; r < 4; r++) {
            float2 t = k_slab[fs * 4 + r];
            mn = fminf(mn, t.x); mx = fmaxf(mx, t.y);
        }
        SXm[s] = mn; SXM[s] = mx;
    }

    // ---- k = 0: first center is original point 0 ----
    int pos0 = s_inv[0];
    float qx = sx[pos0], qy = sy[pos0], qz = sz[pos0];
    if (tid == 0) {
        g_center[b * NG] = make_float4(qx, qy, qz, sumsq3(qx, qy, qz));
        if (out_size >= C_OFF + C_SZ) {
            out[C_OFF + (size_t)(b * NG) * 3 + 0] = qx;
            out[C_OFF + (size_t)(b * NG) * 3 + 1] = qy;
            out[C_OFF + (size_t)(b * NG) * 3 + 2] = qz;
        }
    }

    unsigned wvb = 0; int cand = 0x7fffffff;   // per-warp cached partial
    for (int k = 1; k < NG; k++) {
        const unsigned long long nx = pk2(-qx, -qx);
        const unsigned long long ny = pk2(-qy, -qy);
        const unsigned long long nz = pk2(-qz, -qz);
        bool touched = false;
#pragma unroll
        for (int s = 0; s < 4; s++) {
            float lb = fmaxf(fmaxf(SXm[s] - qx, qx - SXM[s]), 0.0f);
            // skip iff 0.98*lb^2 > slabMax  (conservative: skipped dists unchanged)
            if (!(__fmul_rn(__fmul_rn(lb, lb), 0.98f) > __uint_as_float(SMb[s]))) {
                touched = true;
                unsigned long long dx = add2(P[s][0], nx);
                unsigned long long dy = add2(P[s][1], ny);
                unsigned long long dz = add2(P[s][2], nz);
                unsigned long long t = mul2(dx, dx);
                t = fma2(dy, dy, t);
                t = fma2(dz, dz, t);
                float d0, d1; upk2(t, d0, d1);
                dx = add2(P[s][3], nx); dy = add2(P[s][4], ny); dz = add2(P[s][5], nz);
                t = mul2(dx, dx); t = fma2(dy, dy, t); t = fma2(dz, dz, t);
                float d2, d3; upk2(t, d2, d3);
                float n0 = fminf(D[4 * s + 0], d0); D[4 * s + 0] = n0;
                float n1 = fminf(D[4 * s + 1], d1); D[4 * s + 1] = n1;
                float n2 = fminf(D[4 * s + 2], d2); D[4 * s + 2] = n2;
                float n3 = fminf(D[4 * s + 3], d3); D[4 * s + 3] = n3;
                float m = fmaxf(fmaxf(n0, n1), fmaxf(n2, n3));
                SMb[s] = __reduce_max_sync(FULLMASK, __float_as_uint(m));
            }
        }
        if (touched) {                     // recompute warp partial (exact)
            unsigned m01 = SMb[0] > SMb[1] ? SMb[0] : SMb[1];
            unsigned m23 = SMb[2] > SMb[3] ? SMb[2] : SMb[3];
            wvb = m01 > m23 ? m01 : m23;
            const float wv = __uint_as_float(wvb);
            cand = 0x7fffffff;
#pragma unroll
            for (int s = 0; s < 4; s++) {
                if (SMb[s] == wvb) {       // warp-uniform branch
                    const int p0 = (w * 4 + s) * 128 + lane;
                    int ci = 0x7fffffff;
                    if (D[4 * s + 0] == wv) ci = s_oidx[p0];
                    if (D[4 * s + 1] == wv) ci = min(ci, s_oidx[p0 + 32]);
                    if (D[4 * s + 2] == wv) ci = min(ci, s_oidx[p0 + 64]);
                    if (D[4 * s + 3] == wv) ci = min(ci, s_oidx[p0 + 96]);
                    cand = min(cand, (int)__reduce_min_sync(FULLMASK, (unsigned)ci));
                }
            }
        }
        const int slot = (k & 1) << 4;
        if (lane == 0) { sv[slot + w] = wvb; sidxp[slot + w] = (unsigned)cand; }
        __syncthreads();
        int l = slot + (lane & 15);
        unsigned pv = sv[l], pi = sidxp[l];
        unsigned M2 = __reduce_max_sync(FULLMASK, pv);
        unsigned c2 = (pv == M2) ? pi : 0xffffffffu;
        unsigned forig = __reduce_min_sync(FULLMASK, c2);
        int pos = s_inv[forig];
        qx = sx[pos]; qy = sy[pos]; qz = sz[pos];
        if (tid == 0) {
            g_center[b * NG + k] = make_float4(qx, qy, qz, sumsq3(qx, qy, qz));
            if (out_size >= C_OFF + C_SZ) {
                out[C_OFF + (size_t)(b * NG + k) * 3 + 0] = qx;
                out[C_OFF + (size_t)(b * NG + k) * 3 + 1] = qy;
                out[C_OFF + (size_t)(b * NG + k) * 3 + 2] = qz;
            }
            if ((k & 7) == 7 || k == NG - 1) {
                __threadfence();
                atomicExch(&g_prog[b], k);
            }
        }
    }
}

// ---------------------------------------------------------------------------
// kNN role (unchanged from R9 passing): 16 warps = 8 pair-groups x 4 rounds,
// slab-pruned outward scan + buffered bitonic merges; exact under (d2, idx).
// ---------------------------------------------------------------------------
__device__ __forceinline__ float ref_dist(float4 c, float x, float y, float z, float p2) {
    float dot = __fmul_rn(c.x, x);
    dot = __fmaf_rn(c.y, y, dot);
    dot = __fmaf_rn(c.z, z, dot);
    return __fsub_rn(__fadd_rn(c.w, p2), __fmul_rn(2.0f, dot));
}
__device__ __forceinline__ bool key_less(float ad, int ai, float bd, int bi) {
    return (ad < bd) || (ad == bd && ai < bi);
}
__device__ __forceinline__ void sort32(float& Sd, int& Si, int lane) {
#pragma unroll
    for (int k = 2; k <= 32; k <<= 1) {
        const bool dd = (lane & k) != 0;
#pragma unroll
        for (int j = k >> 1; j > 0; j >>= 1) {
            float od = __shfl_xor_sync(FULLMASK, Sd, j);
            int   oi = __shfl_xor_sync(FULLMASK, Si, j);
            bool lower = key_less(od, oi, Sd, Si);
            bool takeSmaller = (((lane & j) == 0) != dd);
            if (lower == takeSmaller) { Sd = od; Si = oi; }
        }
    }
}
__device__ __forceinline__ void bitonic_cleanup(float& Sd, int& Si, int lane) {
#pragma unroll
    for (int j = 16; j > 0; j >>= 1) {
        float od = __shfl_xor_sync(FULLMASK, Sd, j);
        int   oi = __shfl_xor_sync(FULLMASK, Si, j);
        bool lower = key_less(od, oi, Sd, Si);
        bool takeSmaller = ((lane & j) == 0);
        if (lower == takeSmaller) { Sd = od; Si = oi; }
    }
}

__device__ void knn_role(const float* __restrict__ xyz, float* __restrict__ out,
                         int out_size, int kc) {
    const int tid  = threadIdx.x;
    const int lane = tid & 31;
    const int w    = tid >> 5;
    const int gib  = w >> 1;
    const int role = w & 1;
    const int b    = kc >> 4;
    const int cib  = kc & 15;
    const unsigned lmlt = (1u << lane) - 1u;

    if (lane == 0) { while (atomicAdd(&g_sort_done[b], 0) == 0) __nanosleep(1000); }
    __syncwarp();
    if (tid < NSLAB) k_slab[tid] = g_slab[b * NSLAB + tid];
    __syncthreads();

    const float4* sp = g_spts + b * NPTS;
    const int*    si = g_sidx + b * NPTS;

    for (int t = 0; t < 4; t++) {
        const int k_id = t * 128 + cib * 8 + gib;
        const int grp  = b * NG + k_id;
        if (lane == 0) { while (atomicAdd(&g_prog[b], 0) < k_id) __nanosleep(400); }
        __syncwarp();
        const float4 c = __ldcg(&g_center[grp]);

        int cnt = 0;
#pragma unroll
        for (int r = 0; r < 8; r++) {
            float2 sl = k_slab[r * 32 + lane];
            cnt += __popc(__ballot_sync(FULLMASK, sl.x <= c.x));
        }
        const int s0 = cnt > 0 ? cnt - 1 : 0;

        float Sd = PINF; int Si = 0x7fffffff;
        float Td = PINF; int Ti = 0x7fffffff;
        int bcnt = 0;

        auto merge_buf = [&](int take) {
            float bd = (lane < take) ? k_bufD[w][lane] : PINF;
            int   bi = (lane < take) ? k_bufI[w][lane] : 0x7fffffff;
            sort32(bd, bi, lane);
            float rd = __shfl_sync(FULLMASK, bd, 31 - lane);
            int   ri = __shfl_sync(FULLMASK, bi, 31 - lane);
            if (key_less(rd, ri, Sd, Si)) { Sd = rd; Si = ri; }
            bitonic_cleanup(Sd, Si, lane);
            int rem = bcnt - take;
            if (lane < rem) { k_bufD[w][lane] = k_bufD[w][32 + lane]; k_bufI[w][lane] = k_bufI[w][32 + lane]; }
            bcnt = rem;
            Td = __shfl_sync(FULLMASK, Sd, 31);
            Ti = __shfl_sync(FULLMASK, Si, 31);
        };

        auto process = [&](int s) {
            float2 sl = k_slab[s];
            float lb = fmaxf(fmaxf(sl.x - c.x, c.x - sl.y), 0.0f);
            if (__fmul_rn(__fmul_rn(lb, lb), 0.98f) > Td) return;
            const int base = s * 32;
            float4 p = sp[base + lane];
            int    oi = si[base + lane];
            float d = ref_dist(c, p.x, p.y, p.z, p.w);
            bool qf = key_less(d, oi, Td, Ti);
            unsigned m = __ballot_sync(FULLMASK, qf);
            if (m) {
                int pos = bcnt + __popc(m & lmlt);
                if (qf) { k_bufD[w][pos] = d; k_bufI[w][pos] = oi; }
                bcnt += __popc(m);
                if (bcnt >= 32) merge_buf(32);
            }
        };

        if (role == 0) { for (int s = s0; s < NSLAB; s++) process(s); }
        else           { for (int s = s0 - 1; s >= 0; s--) process(s); }
        if (bcnt > 0) merge_buf(bcnt);

        if (role == 1) { k_mD[gib][lane] = Sd; k_mI[gib][lane] = Si; }
        asm volatile("bar.sync %0, %1;" :: "r"(gib + 1), "r"(64) : "memory");
        if (role == 0) {
            float rd = k_mD[gib][31 - lane];
            int   ri = k_mI[gib][31 - lane];
            if (key_less(rd, ri, Sd, Si)) { Sd = rd; Si = ri; }
            bitonic_cleanup(Sd, Si, lane);

            const int n = Si;
            float4 pw = g_pts[b * NPTS + n];
            const float* pb = xyz + ((size_t)b * NPTS + n) * CDIM;
            float e0 = pb[3], e1 = pb[4], e2 = pb[5];
            float2 w0 = make_float2(pw.x - c.x, pw.y - c.y);
            float2 w1 = make_float2(pw.z - c.z, e0);
            float2 w2 = make_float2(e1, e2);
            float2* ob = (float2*)out + ((size_t)grp * GS + lane) * 3;
            ob[0] = w0; ob[1] = w1; ob[2] = w2;
            if (out_size >= I_OFF + I_SZ)
                out[I_OFF + (size_t)grp * GS + lane] = (float)n;
        }
        asm volatile("bar.sync %0, %1;" :: "r"(gib + 1), "r"(64) : "memory");
    }
}

// ---------------------------------------------------------------------------
__global__ void init_kernel() {
    int i = threadIdx.x;
    if (i < BATCH) { g_prog[i] = -1; g_sort_done[i] = 0; }
}

extern __shared__ char dyn_smem[];
__global__ void __launch_bounds__(FT, 1)
fused_kernel(const float* __restrict__ xyz, float* __restrict__ out, int out_size) {
    const int bid = blockIdx.x;
    if (bid < 8) fps_role(xyz, out, out_size, bid, dyn_smem);
    else         knn_role(xyz, out, out_size, bid - 8);
}

extern "C" void kernel_launch(void* const* d_in, const int* in_sizes, int n_in,
                              void* d_out, int out_size) {
    const float* xyz = (const float*)d_in[0];
    float* out = (float*)d_out;
    (void)in_sizes; (void)n_in;

    cudaFuncSetAttribute(fused_kernel, cudaFuncAttributeMaxDynamicSharedMemorySize,
                         (int)FPS_SMEM);
    init_kernel<<<1, 32>>>();
    fused_kernel<<<136, FT, FPS_SMEM>>>(xyz, out, out_size);
}